// round 2
// baseline (speedup 1.0000x reference)
#include <cuda_runtime.h>
#include <math.h>

#define BSZ 4
#define SQ  1024
#define EMB 1024
#define NH  16
#define HD  64
#define BH  (BSZ*NH)

// Scratch (allocation-free: __device__ globals)
__device__ float g_Q[BSZ*NH*SQ*HD];
__device__ float g_K[BSZ*NH*SQ*HD];
__device__ float g_V[BSZ*NH*SQ*HD];
__device__ float g_O[BSZ*SQ*EMB];

typedef unsigned long long u64;

__device__ __forceinline__ u64 pk2(float a, float b) {
    u64 r; asm("mov.b64 %0,{%1,%2};" : "=l"(r) : "f"(a), "f"(b)); return r;
}
__device__ __forceinline__ void fma2(u64& d, u64 a, u64 b) {
    asm("fma.rn.f32x2 %0,%1,%2,%0;" : "+l"(d) : "l"(a), "l"(b));
}
__device__ __forceinline__ u64 mul2(u64 a, u64 b) {
    u64 r; asm("mul.rn.f32x2 %0,%1,%2;" : "=l"(r) : "l"(a), "l"(b)); return r;
}
__device__ __forceinline__ float2 up2(u64 v) {
    float2 f; asm("mov.b64 {%0,%1},%2;" : "=f"(f.x), "=f"(f.y) : "l"(v)); return f;
}

// ---------------------------------------------------------------------------
// GEMM core: C[128x128] tile of A[M,K] @ B[K,N]; 256 threads, 8x8 per thread,
// accumulation in packed f32x2 (acc[i][p] holds output cols (p*2, p*2+1)).
// ---------------------------------------------------------------------------
__device__ __forceinline__ void gemm_core(
    const float* __restrict__ A, int lda,
    const float* __restrict__ B, int ldb,
    int bm, int bn, int K, u64 acc[8][4])
{
    __shared__ __align__(16) float As[8][128];
    __shared__ __align__(16) float Bs[8][128];

    const int tid  = threadIdx.x;          // 0..255
    const int arow = tid >> 1;             // 0..127
    const int acol = (tid & 1) * 4;        // 0 or 4
    const int brow = tid >> 5;             // 0..7
    const int bcol = (tid & 31) * 4;       // 0..124
    const int ty   = tid >> 4;             // 0..15
    const int tx   = tid & 15;             // 0..15

    #pragma unroll
    for (int i = 0; i < 8; i++)
        #pragma unroll
        for (int p = 0; p < 4; p++) acc[i][p] = 0ULL;

    const float* Ap = A + (long)(bm + arow) * lda + acol;
    const float* Bp = B + (long)brow * ldb + bn + bcol;

    for (int k0 = 0; k0 < K; k0 += 8) {
        float4 av = *(const float4*)Ap; Ap += 8;
        float4 bv = *(const float4*)Bp; Bp += 8 * (long)ldb;
        As[acol + 0][arow] = av.x;
        As[acol + 1][arow] = av.y;
        As[acol + 2][arow] = av.z;
        As[acol + 3][arow] = av.w;
        *(float4*)&Bs[brow][bcol] = bv;
        __syncthreads();

        #pragma unroll
        for (int kk = 0; kk < 8; kk++) {
            float4 a0 = *(const float4*)&As[kk][ty * 8];
            float4 a1 = *(const float4*)&As[kk][ty * 8 + 4];
            ulonglong2 b0 = *(const ulonglong2*)&Bs[kk][tx * 8];
            ulonglong2 b1 = *(const ulonglong2*)&Bs[kk][tx * 8 + 4];
            float ar[8] = {a0.x, a0.y, a0.z, a0.w, a1.x, a1.y, a1.z, a1.w};
            #pragma unroll
            for (int i = 0; i < 8; i++) {
                u64 ai = pk2(ar[i], ar[i]);
                fma2(acc[i][0], ai, b0.x);
                fma2(acc[i][1], ai, b0.y);
                fma2(acc[i][2], ai, b1.x);
                fma2(acc[i][3], ai, b1.y);
            }
        }
        __syncthreads();
    }
}

// ---------------------------------------------------------------------------
// QKV GEMM: qkv = x @ W_attn + b_attn, scattered into [B,H,S,D] Q/K/V.
// Q pre-scaled by 1/sqrt(HD).
// ---------------------------------------------------------------------------
__global__ __launch_bounds__(256, 2) void k_qkv(
    const float* __restrict__ X, const float* __restrict__ W,
    const float* __restrict__ bias)
{
    u64 acc[8][4];
    const int bm = blockIdx.y * 128;
    const int bn = blockIdx.x * 128;
    gemm_core(X, EMB, W, 3 * EMB, bm, bn, EMB, acc);

    const int row0 = bm + (threadIdx.x >> 4) * 8;
    const int col0 = bn + (threadIdx.x & 15) * 8;

    #pragma unroll
    for (int i = 0; i < 8; i++) {
        const int row = row0 + i;
        const int b = row >> 10, s = row & 1023;
        #pragma unroll
        for (int p = 0; p < 4; p++) {
            float2 v = up2(acc[i][p]);
            #pragma unroll
            for (int q = 0; q < 2; q++) {
                const int c = col0 + p * 2 + q;
                float val = (q ? v.y : v.x) + __ldg(&bias[c]);
                const int which = c >> 10;
                const int e = c & 1023;
                const int h = e >> 6, d = e & 63;
                const long idx = (((long)(b * NH + h) * SQ + s) * HD + d);
                if (which == 0)      g_Q[idx] = val * 0.125f;  // 1/sqrt(64)
                else if (which == 1) g_K[idx] = val;
                else                 g_V[idx] = val;
            }
        }
    }
}

// ---------------------------------------------------------------------------
// Causal flash attention: grid (S/64, B*H), 64 threads, 1 q-row per thread.
// K-tiles of 32 keys. fp32 online softmax, f32x2 packed FMA for QK^T and PV.
// Output written in [B,S,E] layout (merged heads) to g_O.
// ---------------------------------------------------------------------------
__global__ __launch_bounds__(64) void k_attn()
{
    __shared__ __align__(16) float qs[64][68];
    __shared__ __align__(16) float ks[32][68];
    __shared__ __align__(16) float vs[32][68];

    const int tid = threadIdx.x;       // 0..63
    const int bh  = blockIdx.y;        // 0..63
    const int q0  = blockIdx.x * 64;
    const int qrow_g = q0 + tid;

    const float* Qb = g_Q + (long)bh * SQ * HD;
    const float* Kb = g_K + (long)bh * SQ * HD;
    const float* Vb = g_V + (long)bh * SQ * HD;

    // Load q rows (each thread its own row)
    {
        const float4* src = (const float4*)(Qb + (long)qrow_g * HD);
        #pragma unroll
        for (int c = 0; c < 16; c++) *(float4*)&qs[tid][c * 4] = src[c];
    }

    u64 o2[32];
    #pragma unroll
    for (int i = 0; i < 32; i++) o2[i] = 0ULL;
    float m = -INFINITY, l = 0.f;

    const int nkt = (q0 >> 5) + 2;  // causal: tiles covering [0, q0+64)
    for (int kt = 0; kt < nkt; kt++) {
        const int k0 = kt * 32;
        __syncthreads();
        // Load K,V tiles (32 rows x 64 floats = 512 float4 each)
        {
            const float4* Ksrc = (const float4*)(Kb + (long)k0 * HD);
            const float4* Vsrc = (const float4*)(Vb + (long)k0 * HD);
            #pragma unroll
            for (int i = 0; i < 8; i++) {
                const int lin = i * 64 + tid;
                const int r = lin >> 4, c = lin & 15;
                *(float4*)&ks[r][c * 4] = Ksrc[lin];
                *(float4*)&vs[r][c * 4] = Vsrc[lin];
            }
        }
        __syncthreads();

        // Scores: s[j] = q . k_j   (f32x2 over the d dimension, chunks of 8 j)
        float sc[32];
        #pragma unroll
        for (int jc = 0; jc < 4; jc++) {
            u64 s2[8];
            #pragma unroll
            for (int j8 = 0; j8 < 8; j8++) s2[j8] = 0ULL;
            #pragma unroll
            for (int d4 = 0; d4 < 16; d4++) {
                ulonglong2 q2 = *(const ulonglong2*)&qs[tid][d4 * 4];
                #pragma unroll
                for (int j8 = 0; j8 < 8; j8++) {
                    ulonglong2 k2 = *(const ulonglong2*)&ks[jc * 8 + j8][d4 * 4];
                    fma2(s2[j8], q2.x, k2.x);
                    fma2(s2[j8], q2.y, k2.y);
                }
            }
            #pragma unroll
            for (int j8 = 0; j8 < 8; j8++) {
                float2 f = up2(s2[j8]);
                sc[jc * 8 + j8] = f.x + f.y;
            }
        }

        // Causal mask + online softmax
        float mnew = m;
        #pragma unroll
        for (int j = 0; j < 32; j++) {
            if (k0 + j > qrow_g) sc[j] = -INFINITY;
            mnew = fmaxf(mnew, sc[j]);
        }
        const float corr = __expf(m - mnew);
        m = mnew;
        float psum = 0.f;
        #pragma unroll
        for (int j = 0; j < 32; j++) {
            sc[j] = __expf(sc[j] - mnew);
            psum += sc[j];
        }
        l = l * corr + psum;
        const u64 c2 = pk2(corr, corr);
        #pragma unroll
        for (int i = 0; i < 32; i++) o2[i] = mul2(o2[i], c2);

        // PV accumulate
        #pragma unroll
        for (int j = 0; j < 32; j++) {
            u64 pj = pk2(sc[j], sc[j]);
            #pragma unroll
            for (int d4 = 0; d4 < 16; d4++) {
                ulonglong2 v2 = *(const ulonglong2*)&vs[j][d4 * 4];
                fma2(o2[d4 * 2 + 0], pj, v2.x);
                fma2(o2[d4 * 2 + 1], pj, v2.y);
            }
        }
    }

    // Finalize and write in [B, S, E] merged-head layout
    const float inv = 1.f / l;
    const int b = bh >> 4, h = bh & 15;
    float* Op = g_O + ((long)(b * SQ + qrow_g)) * EMB + h * HD;
    #pragma unroll
    for (int i = 0; i < 32; i++) {
        float2 f = up2(o2[i]);
        *(float2*)&Op[i * 2] = make_float2(f.x * inv, f.y * inv);
    }
}

// ---------------------------------------------------------------------------
// Output projection: out = g_O @ W_proj + b_proj
// ---------------------------------------------------------------------------
__global__ __launch_bounds__(256, 2) void k_proj(
    const float* __restrict__ W, const float* __restrict__ bias,
    float* __restrict__ out)
{
    u64 acc[8][4];
    const int bm = blockIdx.y * 128;
    const int bn = blockIdx.x * 128;
    gemm_core(g_O, EMB, W, EMB, bm, bn, EMB, acc);

    const int row0 = bm + (threadIdx.x >> 4) * 8;
    const int col0 = bn + (threadIdx.x & 15) * 8;

    #pragma unroll
    for (int i = 0; i < 8; i++) {
        const long rbase = (long)(row0 + i) * EMB;
        #pragma unroll
        for (int p = 0; p < 4; p++) {
            float2 v = up2(acc[i][p]);
            const int c = col0 + p * 2;
            float2 o = make_float2(v.x + __ldg(&bias[c]),
                                   v.y + __ldg(&bias[c + 1]));
            *(float2*)&out[rbase + c] = o;
        }
    }
}

// ---------------------------------------------------------------------------
extern "C" void kernel_launch(void* const* d_in, const int* in_sizes, int n_in,
                              void* d_out, int out_size)
{
    const float* x      = (const float*)d_in[0];
    const float* W_attn = (const float*)d_in[1];
    const float* b_attn = (const float*)d_in[2];
    const float* W_proj = (const float*)d_in[3];
    const float* b_proj = (const float*)d_in[4];
    float* out = (float*)d_out;

    k_qkv <<<dim3(24, 32), 256>>>(x, W_attn, b_attn);
    k_attn<<<dim3(16, 64),  64>>>();
    k_proj<<<dim3( 8, 32), 256>>>(W_proj, b_proj, out);
}

// round 5
// speedup vs baseline: 1.6726x; 1.6726x over previous
#include <cuda_runtime.h>
#include <cuda_bf16.h>
#include <math.h>
#include <cstdint>

#define BSZ 4
#define SQ  1024
#define EMB 1024
#define NH  16
#define HD  64

typedef unsigned long long u64;
typedef unsigned short ushortx;

// ---------------------------------------------------------------------------
// Scratch (__device__ globals; allocation-free)
// ---------------------------------------------------------------------------
__device__ float g_Q[BSZ*NH*SQ*HD];
__device__ float g_K[BSZ*NH*SQ*HD];
__device__ float g_V[BSZ*NH*SQ*HD];
__device__ float g_O[BSZ*SQ*EMB];

// bf16 hi/lo split operands
__device__ uint4 g_Xhi4[4096*1024*2/16];
__device__ uint4 g_Xlo4[4096*1024*2/16];
__device__ uint4 g_Ohi4[4096*1024*2/16];
__device__ uint4 g_Olo4[4096*1024*2/16];
__device__ uint4 g_WaThi4[3072*1024*2/16];   // W_attn^T [3072][1024]
__device__ uint4 g_WaTlo4[3072*1024*2/16];
__device__ uint4 g_WpThi4[1024*1024*2/16];   // W_proj^T [1024][1024]
__device__ uint4 g_WpTlo4[1024*1024*2/16];

// ---------------------------------------------------------------------------
// helpers
// ---------------------------------------------------------------------------
__device__ __forceinline__ uint32_t smem_u32(const void* p) {
    uint32_t a;
    asm("{ .reg .u64 t; cvta.to.shared.u64 t, %1; cvt.u32.u64 %0, t; }" : "=r"(a) : "l"(p));
    return a;
}
__device__ __forceinline__ void cpa16(uint32_t dst, const void* src) {
    asm volatile("cp.async.cg.shared.global [%0], [%1], 16;"
                 :: "r"(dst), "l"(__cvta_generic_to_global(src)) : "memory");
}
#define CPA_COMMIT() asm volatile("cp.async.commit_group;" ::: "memory")
#define CPA_WAIT(n)  asm volatile("cp.async.wait_group %0;" :: "n"(n) : "memory")

__device__ __forceinline__ uint32_t lds32(uint32_t addr) {
    uint32_t v; asm volatile("ld.shared.b32 %0,[%1];" : "=r"(v) : "r"(addr)); return v;
}
// m16n8k16 bf16 MMA, fp32 accumulate
__device__ __forceinline__ void mma16816(float* c, const uint32_t* a, const uint32_t* b) {
    asm volatile("mma.sync.aligned.m16n8k16.row.col.f32.bf16.bf16.f32 "
        "{%0,%1,%2,%3}, {%4,%5,%6,%7}, {%8,%9}, {%0,%1,%2,%3};"
        : "+f"(c[0]), "+f"(c[1]), "+f"(c[2]), "+f"(c[3])
        : "r"(a[0]), "r"(a[1]), "r"(a[2]), "r"(a[3]), "r"(b[0]), "r"(b[1]));
}

// f32x2 helpers (SIMT attention)
__device__ __forceinline__ u64 pk2(float a, float b) {
    u64 r; asm("mov.b64 %0,{%1,%2};" : "=l"(r) : "f"(a), "f"(b)); return r;
}
__device__ __forceinline__ void fma2(u64& d, u64 a, u64 b) {
    asm("fma.rn.f32x2 %0,%1,%2,%0;" : "+l"(d) : "l"(a), "l"(b));
}
__device__ __forceinline__ u64 mul2(u64 a, u64 b) {
    u64 r; asm("mul.rn.f32x2 %0,%1,%2;" : "=l"(r) : "l"(a), "l"(b)); return r;
}
__device__ __forceinline__ float2 up2(u64 v) {
    float2 f; asm("mov.b64 {%0,%1},%2;" : "=f"(f.x), "=f"(f.y) : "l"(v)); return f;
}

// ---------------------------------------------------------------------------
// GEMM geometry: 128x128 block, BK=64, 8 warps (2m x 4n), warp tile 64x32
// smem stage: 4 arrays (Ahi, Alo, Bhi, Blo), each 128 rows x 144 bytes
// ---------------------------------------------------------------------------
#define ROWB   144            // padded row stride in bytes (72 halves)
#define ARRB   (128*ROWB)     // 18432 bytes per array
#define STAGEB (4*ARRB)       // 73728 bytes per stage
#define NCHUNK 16             // 1024 / 64

__device__ __forceinline__ void load_chunk(
    uint32_t st, const ushortx* A0, const ushortx* A1,
    const ushortx* B0, const ushortx* B1, int k0, int tid)
{
    const ushortx* srcs[4] = {A0, A1, B0, B1};
    #pragma unroll
    for (int arr = 0; arr < 4; arr++) {
        const ushortx* s = srcs[arr];
        #pragma unroll
        for (int i = 0; i < 4; i++) {
            const int u = i * 256 + tid;      // 0..1023
            const int r = u >> 3, c16 = u & 7;
            cpa16(st + arr * ARRB + r * ROWB + c16 * 16,
                  (const char*)(s + r * 1024 + k0) + c16 * 16);
        }
    }
}

__device__ __forceinline__ void compute_chunk(
    uint32_t st, int wm, int wn, int t4, int tm4, float acc[4][4][4])
{
    #pragma unroll
    for (int ks = 0; ks < 4; ks++) {
        const int kb = ks * 32 + tm4 * 4;     // byte offset of this thread's k pair
        uint32_t Ahi[4][4], Alo[4][4], Bhi[4][2], Blo[4][2];
        #pragma unroll
        for (int mf = 0; mf < 4; mf++) {
            const uint32_t ra = st + (wm * 64 + mf * 16 + t4) * ROWB + kb;
            Ahi[mf][0] = lds32(ra);
            Ahi[mf][1] = lds32(ra + 8 * ROWB);
            Ahi[mf][2] = lds32(ra + 16);
            Ahi[mf][3] = lds32(ra + 8 * ROWB + 16);
            Alo[mf][0] = lds32(ra + ARRB);
            Alo[mf][1] = lds32(ra + ARRB + 8 * ROWB);
            Alo[mf][2] = lds32(ra + ARRB + 16);
            Alo[mf][3] = lds32(ra + ARRB + 8 * ROWB + 16);
        }
        #pragma unroll
        for (int nf = 0; nf < 4; nf++) {
            const uint32_t rb = st + 2 * ARRB + (wn * 32 + nf * 8 + t4) * ROWB + kb;
            Bhi[nf][0] = lds32(rb);
            Bhi[nf][1] = lds32(rb + 16);
            Blo[nf][0] = lds32(rb + ARRB);
            Blo[nf][1] = lds32(rb + ARRB + 16);
        }
        #pragma unroll
        for (int mf = 0; mf < 4; mf++)
            #pragma unroll
            for (int nf = 0; nf < 4; nf++) {
                mma16816(acc[mf][nf], Ahi[mf], Bhi[nf]);
                mma16816(acc[mf][nf], Ahi[mf], Blo[nf]);
                mma16816(acc[mf][nf], Alo[mf], Bhi[nf]);
            }
    }
}

__device__ __forceinline__ void gemm_mainloop(
    uint32_t sm, const ushortx* A0, const ushortx* A1,
    const ushortx* B0, const ushortx* B1,
    int wm, int wn, int t4, int tm4, int tid, float acc[4][4][4])
{
    #pragma unroll
    for (int mf = 0; mf < 4; mf++)
        #pragma unroll
        for (int nf = 0; nf < 4; nf++)
            #pragma unroll
            for (int j = 0; j < 4; j++) acc[mf][nf][j] = 0.f;

    load_chunk(sm, A0, A1, B0, B1, 0, tid);
    CPA_COMMIT();
    for (int c = 0; c < NCHUNK; c++) {
        if (c + 1 < NCHUNK) {
            load_chunk(sm + ((c + 1) & 1) * STAGEB, A0, A1, B0, B1, (c + 1) * 64, tid);
            CPA_COMMIT();
            CPA_WAIT(1);
        } else {
            CPA_WAIT(0);
        }
        __syncthreads();
        compute_chunk(sm + (c & 1) * STAGEB, wm, wn, t4, tm4, acc);
        __syncthreads();
    }
}

// ---------------------------------------------------------------------------
// QKV GEMM: X @ W_attn + b_attn -> scatter to g_Q (x0.125) / g_K / g_V
// grid (24, 32)
// ---------------------------------------------------------------------------
__global__ __launch_bounds__(256, 1) void k_gemm_qkv(const float* __restrict__ bias)
{
    extern __shared__ char dsm[];
    const int tid = threadIdx.x, wid = tid >> 5, lane = tid & 31;
    const int t4 = lane >> 2, tm4 = lane & 3;
    const int wm = wid >> 2, wn = wid & 3;
    const int bn = blockIdx.x * 128, bm = blockIdx.y * 128;
    const uint32_t sm = smem_u32(dsm);

    float acc[4][4][4];
    gemm_mainloop(sm,
        (const ushortx*)g_Xhi4 + (long)bm * 1024, (const ushortx*)g_Xlo4 + (long)bm * 1024,
        (const ushortx*)g_WaThi4 + (long)bn * 1024, (const ushortx*)g_WaTlo4 + (long)bn * 1024,
        wm, wn, t4, tm4, tid, acc);

    const int which = bn >> 10;             // 0=Q 1=K 2=V (uniform per block)
    float* dst = (which == 0) ? g_Q : (which == 1) ? g_K : g_V;
    const float scale = (which == 0) ? 0.125f : 1.f;

    #pragma unroll
    for (int mf = 0; mf < 4; mf++) {
        #pragma unroll
        for (int nf = 0; nf < 4; nf++) {
            const int n_g = bn + wn * 32 + nf * 8 + tm4 * 2;
            const int e = n_g & 1023, h = e >> 6, d = e & 63;
            const float b0 = __ldg(&bias[n_g]), b1 = __ldg(&bias[n_g + 1]);
            #pragma unroll
            for (int rr = 0; rr < 2; rr++) {
                const int row = bm + wm * 64 + mf * 16 + t4 + rr * 8;
                const int b = row >> 10, s = row & 1023;
                const long off = (((long)(b * NH + h) * SQ) + s) * HD + d;
                float2 v = make_float2((acc[mf][nf][rr * 2 + 0] + b0) * scale,
                                       (acc[mf][nf][rr * 2 + 1] + b1) * scale);
                *(float2*)&dst[off] = v;
            }
        }
    }
}

// ---------------------------------------------------------------------------
// Proj GEMM: g_O @ W_proj + b_proj -> out.  grid (8, 32)
// ---------------------------------------------------------------------------
__global__ __launch_bounds__(256, 1) void k_gemm_proj(const float* __restrict__ bias,
                                                      float* __restrict__ out)
{
    extern __shared__ char dsm[];
    const int tid = threadIdx.x, wid = tid >> 5, lane = tid & 31;
    const int t4 = lane >> 2, tm4 = lane & 3;
    const int wm = wid >> 2, wn = wid & 3;
    const int bn = blockIdx.x * 128, bm = blockIdx.y * 128;
    const uint32_t sm = smem_u32(dsm);

    float acc[4][4][4];
    gemm_mainloop(sm,
        (const ushortx*)g_Ohi4 + (long)bm * 1024, (const ushortx*)g_Olo4 + (long)bm * 1024,
        (const ushortx*)g_WpThi4 + (long)bn * 1024, (const ushortx*)g_WpTlo4 + (long)bn * 1024,
        wm, wn, t4, tm4, tid, acc);

    #pragma unroll
    for (int mf = 0; mf < 4; mf++) {
        #pragma unroll
        for (int nf = 0; nf < 4; nf++) {
            const int n_g = bn + wn * 32 + nf * 8 + tm4 * 2;
            const float b0 = __ldg(&bias[n_g]), b1 = __ldg(&bias[n_g + 1]);
            #pragma unroll
            for (int rr = 0; rr < 2; rr++) {
                const int row = bm + wm * 64 + mf * 16 + t4 + rr * 8;
                float2 v = make_float2(acc[mf][nf][rr * 2 + 0] + b0,
                                       acc[mf][nf][rr * 2 + 1] + b1);
                *(float2*)&out[(long)row * EMB + n_g] = v;
            }
        }
    }
}

// ---------------------------------------------------------------------------
// Elementwise f32 -> bf16 hi/lo split
// ---------------------------------------------------------------------------
__global__ __launch_bounds__(256) void k_cvt(const float4* __restrict__ src,
                                             uint2* __restrict__ hi, uint2* __restrict__ lo, int n4)
{
    int i = blockIdx.x * 256 + threadIdx.x;
    if (i >= n4) return;
    float4 v = src[i];
    float vv[4] = {v.x, v.y, v.z, v.w};
    unsigned short h[4], l[4];
    #pragma unroll
    for (int j = 0; j < 4; j++) {
        __nv_bfloat16 bh = __float2bfloat16_rn(vv[j]);
        float r = vv[j] - __bfloat162float(bh);
        __nv_bfloat16 bl = __float2bfloat16_rn(r);
        h[j] = __bfloat16_as_ushort(bh);
        l[j] = __bfloat16_as_ushort(bl);
    }
    hi[i] = make_uint2((uint32_t)h[0] | ((uint32_t)h[1] << 16),
                       (uint32_t)h[2] | ((uint32_t)h[3] << 16));
    lo[i] = make_uint2((uint32_t)l[0] | ((uint32_t)l[1] << 16),
                       (uint32_t)l[2] | ((uint32_t)l[3] << 16));
}

// ---------------------------------------------------------------------------
// Transpose-convert: W [1024, ncols] f32 -> W^T hi/lo [ncols, 1024] bf16
// ---------------------------------------------------------------------------
__global__ __launch_bounds__(256) void k_wT(const float* __restrict__ W, int ncols,
                                            ushortx* __restrict__ hiT,
                                            ushortx* __restrict__ loT)
{
    __shared__ float t[32][33];
    const int tx = threadIdx.x, ty = threadIdx.y;     // 32 x 8
    const int n0 = blockIdx.x * 32, k0 = blockIdx.y * 32;
    #pragma unroll
    for (int i = 0; i < 4; i++)
        t[ty + i * 8][tx] = W[(k0 + ty + i * 8) * ncols + n0 + tx];
    __syncthreads();
    #pragma unroll
    for (int i = 0; i < 4; i++) {
        const int r = ty + i * 8;
        float v = t[tx][r];
        __nv_bfloat16 bh = __float2bfloat16_rn(v);
        float rr = v - __bfloat162float(bh);
        __nv_bfloat16 bl = __float2bfloat16_rn(rr);
        const int off = (n0 + r) * 1024 + k0 + tx;
        hiT[off] = __bfloat16_as_ushort(bh);
        loT[off] = __bfloat16_as_ushort(bl);
    }
}

// ---------------------------------------------------------------------------
// Causal flash attention (SIMT f32x2): grid (16, 64), 64 threads
// ---------------------------------------------------------------------------
__global__ __launch_bounds__(64) void k_attn()
{
    __shared__ __align__(16) float qs[64][68];
    __shared__ __align__(16) float ks[32][68];
    __shared__ __align__(16) float vs[32][68];

    const int tid = threadIdx.x;
    const int bh  = blockIdx.y;
    const int q0  = blockIdx.x * 64;
    const int qrow_g = q0 + tid;

    const float* Qb = g_Q + (long)bh * SQ * HD;
    const float* Kb = g_K + (long)bh * SQ * HD;
    const float* Vb = g_V + (long)bh * SQ * HD;

    {
        const float4* src = (const float4*)(Qb + (long)qrow_g * HD);
        #pragma unroll
        for (int c = 0; c < 16; c++) *(float4*)&qs[tid][c * 4] = src[c];
    }

    u64 o2[32];
    #pragma unroll
    for (int i = 0; i < 32; i++) o2[i] = 0ULL;
    float m = -INFINITY, l = 0.f;

    const int nkt = (q0 >> 5) + 2;
    for (int kt = 0; kt < nkt; kt++) {
        const int k0 = kt * 32;
        __syncthreads();
        {
            const float4* Ksrc = (const float4*)(Kb + (long)k0 * HD);
            const float4* Vsrc = (const float4*)(Vb + (long)k0 * HD);
            #pragma unroll
            for (int i = 0; i < 8; i++) {
                const int lin = i * 64 + tid;
                const int r = lin >> 4, c = lin & 15;
                *(float4*)&ks[r][c * 4] = Ksrc[lin];
                *(float4*)&vs[r][c * 4] = Vsrc[lin];
            }
        }
        __syncthreads();

        float sc[32];
        #pragma unroll
        for (int jc = 0; jc < 4; jc++) {
            u64 s2[8];
            #pragma unroll
            for (int j8 = 0; j8 < 8; j8++) s2[j8] = 0ULL;
            #pragma unroll
            for (int d4 = 0; d4 < 16; d4++) {
                ulonglong2 q2 = *(const ulonglong2*)&qs[tid][d4 * 4];
                #pragma unroll
                for (int j8 = 0; j8 < 8; j8++) {
                    ulonglong2 k2 = *(const ulonglong2*)&ks[jc * 8 + j8][d4 * 4];
                    fma2(s2[j8], q2.x, k2.x);
                    fma2(s2[j8], q2.y, k2.y);
                }
            }
            #pragma unroll
            for (int j8 = 0; j8 < 8; j8++) {
                float2 f = up2(s2[j8]);
                sc[jc * 8 + j8] = f.x + f.y;
            }
        }

        float mnew = m;
        #pragma unroll
        for (int j = 0; j < 32; j++) {
            if (k0 + j > qrow_g) sc[j] = -INFINITY;
            mnew = fmaxf(mnew, sc[j]);
        }
        const float corr = __expf(m - mnew);
        m = mnew;
        float psum = 0.f;
        #pragma unroll
        for (int j = 0; j < 32; j++) {
            sc[j] = __expf(sc[j] - mnew);
            psum += sc[j];
        }
        l = l * corr + psum;
        const u64 c2 = pk2(corr, corr);
        #pragma unroll
        for (int i = 0; i < 32; i++) o2[i] = mul2(o2[i], c2);

        #pragma unroll
        for (int j = 0; j < 32; j++) {
            u64 pj = pk2(sc[j], sc[j]);
            #pragma unroll
            for (int d4 = 0; d4 < 16; d4++) {
                ulonglong2 v2 = *(const ulonglong2*)&vs[j][d4 * 4];
                fma2(o2[d4 * 2 + 0], pj, v2.x);
                fma2(o2[d4 * 2 + 1], pj, v2.y);
            }
        }
    }

    const float inv = 1.f / l;
    const int b = bh >> 4, h = bh & 15;
    float* Op = g_O + ((long)(b * SQ + qrow_g)) * EMB + h * HD;
    #pragma unroll
    for (int i = 0; i < 32; i++) {
        float2 f = up2(o2[i]);
        *(float2*)&Op[i * 2] = make_float2(f.x * inv, f.y * inv);
    }
}

// ---------------------------------------------------------------------------
extern "C" void kernel_launch(void* const* d_in, const int* in_sizes, int n_in,
                              void* d_out, int out_size)
{
    const float* x      = (const float*)d_in[0];
    const float* W_attn = (const float*)d_in[1];
    const float* b_attn = (const float*)d_in[2];
    const float* W_proj = (const float*)d_in[3];
    const float* b_proj = (const float*)d_in[4];
    float* out = (float*)d_out;

    const int DSM = 2 * STAGEB;   // 147456 bytes
    cudaFuncSetAttribute(k_gemm_qkv,  cudaFuncAttributeMaxDynamicSharedMemorySize, DSM);
    cudaFuncSetAttribute(k_gemm_proj, cudaFuncAttributeMaxDynamicSharedMemorySize, DSM);

    uint4 *xhi, *xlo, *ohi, *olo, *wahi, *walo, *wphi, *wplo;
    cudaGetSymbolAddress((void**)&xhi,  g_Xhi4);
    cudaGetSymbolAddress((void**)&xlo,  g_Xlo4);
    cudaGetSymbolAddress((void**)&ohi,  g_Ohi4);
    cudaGetSymbolAddress((void**)&olo,  g_Olo4);
    cudaGetSymbolAddress((void**)&wahi, g_WaThi4);
    cudaGetSymbolAddress((void**)&walo, g_WaTlo4);
    cudaGetSymbolAddress((void**)&wphi, g_WpThi4);
    cudaGetSymbolAddress((void**)&wplo, g_WpTlo4);
    float* o_f32;
    cudaGetSymbolAddress((void**)&o_f32, g_O);

    k_cvt<<<4096, 256>>>((const float4*)x, (uint2*)xhi, (uint2*)xlo, 4096 * 1024 / 4);
    k_wT<<<dim3(96, 32), dim3(32, 8)>>>(W_attn, 3072, (ushortx*)wahi, (ushortx*)walo);
    k_wT<<<dim3(32, 32), dim3(32, 8)>>>(W_proj, 1024, (ushortx*)wphi, (ushortx*)wplo);
    k_gemm_qkv<<<dim3(24, 32), 256, DSM>>>(b_attn);
    k_attn<<<dim3(16, 64), 64>>>();
    k_cvt<<<4096, 256>>>((const float4*)o_f32, (uint2*)ohi, (uint2*)olo, 4096 * 1024 / 4);
    k_gemm_proj<<<dim3(8, 32), 256, DSM>>>(b_proj, out);
}

// round 6
// speedup vs baseline: 2.7982x; 1.6729x over previous
#include <cuda_runtime.h>
#include <cuda_bf16.h>
#include <math.h>
#include <cstdint>

#define BSZ 4
#define SQ  1024
#define EMB 1024
#define NH  16
#define HD  64

typedef unsigned long long u64;
typedef unsigned short ushortx;

// ---------------------------------------------------------------------------
// Scratch (__device__ globals; allocation-free)
// ---------------------------------------------------------------------------
__device__ float g_Q[BSZ*NH*SQ*HD];
__device__ float g_K[BSZ*NH*SQ*HD];
__device__ float g_V[BSZ*NH*SQ*HD];

// bf16 hi/lo split operands
__device__ uint4 g_Xhi4[4096*1024*2/16];
__device__ uint4 g_Xlo4[4096*1024*2/16];
__device__ uint4 g_Ohi4[4096*1024*2/16];
__device__ uint4 g_Olo4[4096*1024*2/16];
__device__ uint4 g_WaThi4[3072*1024*2/16];   // W_attn^T [3072][1024]
__device__ uint4 g_WaTlo4[3072*1024*2/16];
__device__ uint4 g_WpThi4[1024*1024*2/16];   // W_proj^T [1024][1024]
__device__ uint4 g_WpTlo4[1024*1024*2/16];

// ---------------------------------------------------------------------------
// helpers
// ---------------------------------------------------------------------------
__device__ __forceinline__ uint32_t smem_u32(const void* p) {
    uint32_t a;
    asm("{ .reg .u64 t; cvta.to.shared.u64 t, %1; cvt.u32.u64 %0, t; }" : "=r"(a) : "l"(p));
    return a;
}
__device__ __forceinline__ void cpa16(uint32_t dst, const void* src) {
    asm volatile("cp.async.cg.shared.global [%0], [%1], 16;"
                 :: "r"(dst), "l"(__cvta_generic_to_global(src)) : "memory");
}
#define CPA_COMMIT() asm volatile("cp.async.commit_group;" ::: "memory")
#define CPA_WAIT(n)  asm volatile("cp.async.wait_group %0;" :: "n"(n) : "memory")

__device__ __forceinline__ uint32_t lds32(uint32_t addr) {
    uint32_t v; asm volatile("ld.shared.b32 %0,[%1];" : "=r"(v) : "r"(addr)); return v;
}
// m16n8k16 bf16 MMA, fp32 accumulate
__device__ __forceinline__ void mma16816(float* c, const uint32_t* a, const uint32_t* b) {
    asm volatile("mma.sync.aligned.m16n8k16.row.col.f32.bf16.bf16.f32 "
        "{%0,%1,%2,%3}, {%4,%5,%6,%7}, {%8,%9}, {%0,%1,%2,%3};"
        : "+f"(c[0]), "+f"(c[1]), "+f"(c[2]), "+f"(c[3])
        : "r"(a[0]), "r"(a[1]), "r"(a[2]), "r"(a[3]), "r"(b[0]), "r"(b[1]));
}
__device__ __forceinline__ void ldm_x4(uint32_t* r, uint32_t addr) {
    asm volatile("ldmatrix.sync.aligned.m8n8.x4.shared.b16 {%0,%1,%2,%3}, [%4];"
        : "=r"(r[0]), "=r"(r[1]), "=r"(r[2]), "=r"(r[3]) : "r"(addr));
}
__device__ __forceinline__ void ldm_x2(uint32_t* r, uint32_t addr) {
    asm volatile("ldmatrix.sync.aligned.m8n8.x2.shared.b16 {%0,%1}, [%2];"
        : "=r"(r[0]), "=r"(r[1]) : "r"(addr));
}
__device__ __forceinline__ void ldm_x2t(uint32_t* r, uint32_t addr) {
    asm volatile("ldmatrix.sync.aligned.m8n8.x2.trans.shared.b16 {%0,%1}, [%2];"
        : "=r"(r[0]), "=r"(r[1]) : "r"(addr));
}
// two f32 -> packed bf16x2 hi + residual lo
__device__ __forceinline__ void split2(float x, float y, uint32_t& h, uint32_t& l) {
    __nv_bfloat16 hx = __float2bfloat16_rn(x);
    __nv_bfloat16 hy = __float2bfloat16_rn(y);
    float rx = x - __bfloat162float(hx);
    float ry = y - __bfloat162float(hy);
    __nv_bfloat16 lx = __float2bfloat16_rn(rx);
    __nv_bfloat16 ly = __float2bfloat16_rn(ry);
    h = (uint32_t)__bfloat16_as_ushort(hx) | ((uint32_t)__bfloat16_as_ushort(hy) << 16);
    l = (uint32_t)__bfloat16_as_ushort(lx) | ((uint32_t)__bfloat16_as_ushort(ly) << 16);
}

// ---------------------------------------------------------------------------
// GEMM geometry: 128x128 block, BK=64, 8 warps (2m x 4n), warp tile 64x32
// smem stage: 4 arrays (Ahi, Alo, Bhi, Blo), each 128 rows x 144 bytes
// ---------------------------------------------------------------------------
#define ROWB   144
#define ARRB   (128*ROWB)
#define STAGEB (4*ARRB)
#define NCHUNK 16

__device__ __forceinline__ void load_chunk(
    uint32_t st, const ushortx* A0, const ushortx* A1,
    const ushortx* B0, const ushortx* B1, int k0, int tid)
{
    const ushortx* srcs[4] = {A0, A1, B0, B1};
    #pragma unroll
    for (int arr = 0; arr < 4; arr++) {
        const ushortx* s = srcs[arr];
        #pragma unroll
        for (int i = 0; i < 4; i++) {
            const int u = i * 256 + tid;
            const int r = u >> 3, c16 = u & 7;
            cpa16(st + arr * ARRB + r * ROWB + c16 * 16,
                  (const char*)(s + r * 1024 + k0) + c16 * 16);
        }
    }
}

__device__ __forceinline__ void compute_chunk(
    uint32_t st, int wm, int wn, int t4, int tm4, float acc[4][4][4])
{
    #pragma unroll
    for (int ks = 0; ks < 4; ks++) {
        const int kb = ks * 32 + tm4 * 4;
        uint32_t Ahi[4][4], Alo[4][4], Bhi[4][2], Blo[4][2];
        #pragma unroll
        for (int mf = 0; mf < 4; mf++) {
            const uint32_t ra = st + (wm * 64 + mf * 16 + t4) * ROWB + kb;
            Ahi[mf][0] = lds32(ra);
            Ahi[mf][1] = lds32(ra + 8 * ROWB);
            Ahi[mf][2] = lds32(ra + 16);
            Ahi[mf][3] = lds32(ra + 8 * ROWB + 16);
            Alo[mf][0] = lds32(ra + ARRB);
            Alo[mf][1] = lds32(ra + ARRB + 8 * ROWB);
            Alo[mf][2] = lds32(ra + ARRB + 16);
            Alo[mf][3] = lds32(ra + ARRB + 8 * ROWB + 16);
        }
        #pragma unroll
        for (int nf = 0; nf < 4; nf++) {
            const uint32_t rb = st + 2 * ARRB + (wn * 32 + nf * 8 + t4) * ROWB + kb;
            Bhi[nf][0] = lds32(rb);
            Bhi[nf][1] = lds32(rb + 16);
            Blo[nf][0] = lds32(rb + ARRB);
            Blo[nf][1] = lds32(rb + ARRB + 16);
        }
        #pragma unroll
        for (int mf = 0; mf < 4; mf++)
            #pragma unroll
            for (int nf = 0; nf < 4; nf++) {
                mma16816(acc[mf][nf], Ahi[mf], Bhi[nf]);
                mma16816(acc[mf][nf], Ahi[mf], Blo[nf]);
                mma16816(acc[mf][nf], Alo[mf], Bhi[nf]);
            }
    }
}

__device__ __forceinline__ void gemm_mainloop(
    uint32_t sm, const ushortx* A0, const ushortx* A1,
    const ushortx* B0, const ushortx* B1,
    int wm, int wn, int t4, int tm4, int tid, float acc[4][4][4])
{
    #pragma unroll
    for (int mf = 0; mf < 4; mf++)
        #pragma unroll
        for (int nf = 0; nf < 4; nf++)
            #pragma unroll
            for (int j = 0; j < 4; j++) acc[mf][nf][j] = 0.f;

    load_chunk(sm, A0, A1, B0, B1, 0, tid);
    CPA_COMMIT();
    for (int c = 0; c < NCHUNK; c++) {
        if (c + 1 < NCHUNK) {
            load_chunk(sm + ((c + 1) & 1) * STAGEB, A0, A1, B0, B1, (c + 1) * 64, tid);
            CPA_COMMIT();
            CPA_WAIT(1);
        } else {
            CPA_WAIT(0);
        }
        __syncthreads();
        compute_chunk(sm + (c & 1) * STAGEB, wm, wn, t4, tm4, acc);
        __syncthreads();
    }
}

// ---------------------------------------------------------------------------
// QKV GEMM: X @ W_attn + b_attn -> scatter to g_Q (x0.125) / g_K / g_V
// ---------------------------------------------------------------------------
__global__ __launch_bounds__(256, 1) void k_gemm_qkv(const float* __restrict__ bias)
{
    extern __shared__ char dsm[];
    const int tid = threadIdx.x, wid = tid >> 5, lane = tid & 31;
    const int t4 = lane >> 2, tm4 = lane & 3;
    const int wm = wid >> 2, wn = wid & 3;
    const int bn = blockIdx.x * 128, bm = blockIdx.y * 128;
    const uint32_t sm = smem_u32(dsm);

    float acc[4][4][4];
    gemm_mainloop(sm,
        (const ushortx*)g_Xhi4 + (long)bm * 1024, (const ushortx*)g_Xlo4 + (long)bm * 1024,
        (const ushortx*)g_WaThi4 + (long)bn * 1024, (const ushortx*)g_WaTlo4 + (long)bn * 1024,
        wm, wn, t4, tm4, tid, acc);

    const int which = bn >> 10;
    float* dst = (which == 0) ? g_Q : (which == 1) ? g_K : g_V;
    const float scale = (which == 0) ? 0.125f : 1.f;

    #pragma unroll
    for (int mf = 0; mf < 4; mf++) {
        #pragma unroll
        for (int nf = 0; nf < 4; nf++) {
            const int n_g = bn + wn * 32 + nf * 8 + tm4 * 2;
            const int e = n_g & 1023, h = e >> 6, d = e & 63;
            const float b0 = __ldg(&bias[n_g]), b1 = __ldg(&bias[n_g + 1]);
            #pragma unroll
            for (int rr = 0; rr < 2; rr++) {
                const int row = bm + wm * 64 + mf * 16 + t4 + rr * 8;
                const int b = row >> 10, s = row & 1023;
                const long off = (((long)(b * NH + h) * SQ) + s) * HD + d;
                float2 v = make_float2((acc[mf][nf][rr * 2 + 0] + b0) * scale,
                                       (acc[mf][nf][rr * 2 + 1] + b1) * scale);
                *(float2*)&dst[off] = v;
            }
        }
    }
}

// ---------------------------------------------------------------------------
// Proj GEMM: Obf16 @ W_proj + b_proj -> out
// ---------------------------------------------------------------------------
__global__ __launch_bounds__(256, 1) void k_gemm_proj(const float* __restrict__ bias,
                                                      float* __restrict__ out)
{
    extern __shared__ char dsm[];
    const int tid = threadIdx.x, wid = tid >> 5, lane = tid & 31;
    const int t4 = lane >> 2, tm4 = lane & 3;
    const int wm = wid >> 2, wn = wid & 3;
    const int bn = blockIdx.x * 128, bm = blockIdx.y * 128;
    const uint32_t sm = smem_u32(dsm);

    float acc[4][4][4];
    gemm_mainloop(sm,
        (const ushortx*)g_Ohi4 + (long)bm * 1024, (const ushortx*)g_Olo4 + (long)bm * 1024,
        (const ushortx*)g_WpThi4 + (long)bn * 1024, (const ushortx*)g_WpTlo4 + (long)bn * 1024,
        wm, wn, t4, tm4, tid, acc);

    #pragma unroll
    for (int mf = 0; mf < 4; mf++) {
        #pragma unroll
        for (int nf = 0; nf < 4; nf++) {
            const int n_g = bn + wn * 32 + nf * 8 + tm4 * 2;
            const float b0 = __ldg(&bias[n_g]), b1 = __ldg(&bias[n_g + 1]);
            #pragma unroll
            for (int rr = 0; rr < 2; rr++) {
                const int row = bm + wm * 64 + mf * 16 + t4 + rr * 8;
                float2 v = make_float2(acc[mf][nf][rr * 2 + 0] + b0,
                                       acc[mf][nf][rr * 2 + 1] + b1);
                *(float2*)&out[(long)row * EMB + n_g] = v;
            }
        }
    }
}

// ---------------------------------------------------------------------------
// Elementwise f32 -> bf16 hi/lo split
// ---------------------------------------------------------------------------
__global__ __launch_bounds__(256) void k_cvt(const float4* __restrict__ src,
                                             uint2* __restrict__ hi, uint2* __restrict__ lo, int n4)
{
    int i = blockIdx.x * 256 + threadIdx.x;
    if (i >= n4) return;
    float4 v = src[i];
    uint32_t h0, h1, l0, l1;
    split2(v.x, v.y, h0, l0);
    split2(v.z, v.w, h1, l1);
    hi[i] = make_uint2(h0, h1);
    lo[i] = make_uint2(l0, l1);
}

// ---------------------------------------------------------------------------
// Transpose-convert: W [1024, ncols] f32 -> W^T hi/lo [ncols, 1024] bf16
// ---------------------------------------------------------------------------
__global__ __launch_bounds__(256) void k_wT(const float* __restrict__ W, int ncols,
                                            ushortx* __restrict__ hiT,
                                            ushortx* __restrict__ loT)
{
    __shared__ float t[32][33];
    const int tx = threadIdx.x, ty = threadIdx.y;
    const int n0 = blockIdx.x * 32, k0 = blockIdx.y * 32;
    #pragma unroll
    for (int i = 0; i < 4; i++)
        t[ty + i * 8][tx] = W[(k0 + ty + i * 8) * ncols + n0 + tx];
    __syncthreads();
    #pragma unroll
    for (int i = 0; i < 4; i++) {
        const int r = ty + i * 8;
        float v = t[tx][r];
        __nv_bfloat16 bh = __float2bfloat16_rn(v);
        float rr = v - __bfloat162float(bh);
        __nv_bfloat16 bl = __float2bfloat16_rn(rr);
        const int off = (n0 + r) * 1024 + k0 + tx;
        hiT[off] = __bfloat16_as_ushort(bh);
        loT[off] = __bfloat16_as_ushort(bl);
    }
}

// ---------------------------------------------------------------------------
// HMMA causal flash attention.
// Block: 128 q-rows x 1 head. 8 warps x 16 q-rows. 64-key tiles.
// Scores and PV via m16n8k16 bf16 with hi/lo 3-MMA splits.
// Writes O directly as bf16 hi/lo ([B,S,E] merged heads) for the proj GEMM.
// smem (36864B dynamic): during Q stage: Qhi[128][72], Qlo[128][72];
// per k-tile: Khi/Klo/Vhi/Vlo each [64][72] bf16 (AROW=144B rows).
// ---------------------------------------------------------------------------
#define AROW 144

__global__ __launch_bounds__(256, 1) void k_attn_mma()
{
    extern __shared__ char smb[];
    const uint32_t sb = smem_u32(smb);
    const int tid = threadIdx.x, lane = tid & 31, w = tid >> 5;
    const int t4 = lane >> 2, tm4 = lane & 3;
    const int bh = blockIdx.y;
    const int q0 = ((int)gridDim.x - 1 - (int)blockIdx.x) * 128;  // heavy blocks first

    // ---- stage Q (f32 -> bf16 hi/lo in smem)
    const float* Qg = g_Q + ((long)bh * SQ + q0) * HD;
    #pragma unroll
    for (int i = 0; i < 8; i++) {
        const int idx = i * 256 + tid;
        const int r = idx >> 4, c4 = idx & 15;
        float4 v = ((const float4*)Qg)[idx];
        uint32_t h0, h1, l0, l1;
        split2(v.x, v.y, h0, l0);
        split2(v.z, v.w, h1, l1);
        *(uint2*)(smb + r * AROW + c4 * 8) = make_uint2(h0, h1);
        *(uint2*)(smb + 128 * AROW + r * AROW + c4 * 8) = make_uint2(l0, l1);
    }
    __syncthreads();

    // ---- Q fragments (A, m16k16 x4 k-steps), kept in regs for whole kernel
    uint32_t qh[4][4], ql[4][4];
    {
        const uint32_t rowq = w * 16 + (lane & 15);
        #pragma unroll
        for (int ks = 0; ks < 4; ks++) {
            const uint32_t col = ks * 32 + ((lane >> 4) << 4);
            ldm_x4(qh[ks], sb + rowq * AROW + col);
            ldm_x4(ql[ks], sb + 128 * AROW + rowq * AROW + col);
        }
    }
    __syncthreads();   // Q smem area now reusable for K/V

    const uint32_t Khi = sb, Klo = sb + 64 * AROW,
                   Vhi = sb + 128 * AROW, Vlo = sb + 192 * AROW;

    float O[8][4];
    #pragma unroll
    for (int i = 0; i < 8; i++)
        #pragma unroll
        for (int j = 0; j < 4; j++) O[i][j] = 0.f;
    float m0 = -INFINITY, m1 = -INFINITY, lsum0 = 0.f, lsum1 = 0.f;
    const int qrow0 = q0 + w * 16 + t4;   // row of c0/c1; c2/c3 at +8

    const float* Kg = g_K + (long)bh * SQ * HD;
    const float* Vg = g_V + (long)bh * SQ * HD;
    const int nkt = q0 / 64 + 2;

    for (int kt = 0; kt < nkt; kt++) {
        const int k0 = kt * 64;
        // ---- stage K/V tile (f32 -> bf16 hi/lo)
        #pragma unroll
        for (int i = 0; i < 4; i++) {
            const int idx = i * 256 + tid;
            const int r = idx >> 4, c4 = idx & 15;
            float4 kv = ((const float4*)(Kg + (long)k0 * HD))[idx];
            float4 vv = ((const float4*)(Vg + (long)k0 * HD))[idx];
            uint32_t h0, h1, l0, l1;
            split2(kv.x, kv.y, h0, l0);
            split2(kv.z, kv.w, h1, l1);
            *(uint2*)(smb + (Khi - sb) + r * AROW + c4 * 8) = make_uint2(h0, h1);
            *(uint2*)(smb + (Klo - sb) + r * AROW + c4 * 8) = make_uint2(l0, l1);
            split2(vv.x, vv.y, h0, l0);
            split2(vv.z, vv.w, h1, l1);
            *(uint2*)(smb + (Vhi - sb) + r * AROW + c4 * 8) = make_uint2(h0, h1);
            *(uint2*)(smb + (Vlo - sb) + r * AROW + c4 * 8) = make_uint2(l0, l1);
        }
        __syncthreads();

        // ---- scores S = Q K^T (3-MMA split), 8 n-frags of 8 keys
        float sc[8][4];
        #pragma unroll
        for (int nf = 0; nf < 8; nf++) {
            sc[nf][0] = sc[nf][1] = sc[nf][2] = sc[nf][3] = 0.f;
            const uint32_t rowk = nf * 8 + (lane & 7);
            const uint32_t colp = ((lane >> 3) & 1) * 16;
            #pragma unroll
            for (int ks = 0; ks < 4; ks++) {
                uint32_t bh_[2], bl_[2];
                ldm_x2(bh_, Khi + rowk * AROW + ks * 32 + colp);
                ldm_x2(bl_, Klo + rowk * AROW + ks * 32 + colp);
                mma16816(sc[nf], qh[ks], bh_);
                mma16816(sc[nf], qh[ks], bl_);
                mma16816(sc[nf], ql[ks], bh_);
            }
        }

        // ---- causal mask (only the last two tiles can clip)
        if (kt >= nkt - 2) {
            #pragma unroll
            for (int nf = 0; nf < 8; nf++) {
                const int col = k0 + nf * 8 + tm4 * 2;
                if (col     > qrow0)     sc[nf][0] = -1e30f;
                if (col + 1 > qrow0)     sc[nf][1] = -1e30f;
                if (col     > qrow0 + 8) sc[nf][2] = -1e30f;
                if (col + 1 > qrow0 + 8) sc[nf][3] = -1e30f;
            }
        }

        // ---- online softmax (rows t4 and t4+8 within warp)
        float mx0 = sc[0][0], mx1 = sc[0][2];
        #pragma unroll
        for (int nf = 0; nf < 8; nf++) {
            mx0 = fmaxf(mx0, fmaxf(sc[nf][0], sc[nf][1]));
            mx1 = fmaxf(mx1, fmaxf(sc[nf][2], sc[nf][3]));
        }
        mx0 = fmaxf(mx0, __shfl_xor_sync(0xFFFFFFFF, mx0, 1));
        mx0 = fmaxf(mx0, __shfl_xor_sync(0xFFFFFFFF, mx0, 2));
        mx1 = fmaxf(mx1, __shfl_xor_sync(0xFFFFFFFF, mx1, 1));
        mx1 = fmaxf(mx1, __shfl_xor_sync(0xFFFFFFFF, mx1, 2));
        const float mn0 = fmaxf(m0, mx0), mn1 = fmaxf(m1, mx1);
        const float c0 = __expf(m0 - mn0), c1 = __expf(m1 - mn1);
        m0 = mn0; m1 = mn1;
        float ps0 = 0.f, ps1 = 0.f;
        #pragma unroll
        for (int nf = 0; nf < 8; nf++) {
            sc[nf][0] = __expf(sc[nf][0] - mn0); ps0 += sc[nf][0];
            sc[nf][1] = __expf(sc[nf][1] - mn0); ps0 += sc[nf][1];
            sc[nf][2] = __expf(sc[nf][2] - mn1); ps1 += sc[nf][2];
            sc[nf][3] = __expf(sc[nf][3] - mn1); ps1 += sc[nf][3];
        }
        ps0 += __shfl_xor_sync(0xFFFFFFFF, ps0, 1);
        ps0 += __shfl_xor_sync(0xFFFFFFFF, ps0, 2);
        ps1 += __shfl_xor_sync(0xFFFFFFFF, ps1, 1);
        ps1 += __shfl_xor_sync(0xFFFFFFFF, ps1, 2);
        lsum0 = lsum0 * c0 + ps0;
        lsum1 = lsum1 * c1 + ps1;
        #pragma unroll
        for (int nf = 0; nf < 8; nf++) {
            O[nf][0] *= c0; O[nf][1] *= c0;
            O[nf][2] *= c1; O[nf][3] *= c1;
        }

        // ---- pack P as A-frags (hi/lo) directly from score c-frags
        uint32_t ph[4][4], pl[4][4];
        #pragma unroll
        for (int j = 0; j < 4; j++) {
            split2(sc[2*j    ][0], sc[2*j    ][1], ph[j][0], pl[j][0]);
            split2(sc[2*j    ][2], sc[2*j    ][3], ph[j][1], pl[j][1]);
            split2(sc[2*j + 1][0], sc[2*j + 1][1], ph[j][2], pl[j][2]);
            split2(sc[2*j + 1][2], sc[2*j + 1][3], ph[j][3], pl[j][3]);
        }

        // ---- O += P V (3-MMA split); V^T B-frags via ldmatrix.trans
        #pragma unroll
        for (int nfd = 0; nfd < 8; nfd++) {
            #pragma unroll
            for (int ks = 0; ks < 4; ks++) {
                uint32_t bvh[2], bvl[2];
                const uint32_t rowv = ks * 16 + (lane & 15);
                ldm_x2t(bvh, Vhi + rowv * AROW + nfd * 16);
                ldm_x2t(bvl, Vlo + rowv * AROW + nfd * 16);
                mma16816(O[nfd], ph[ks], bvh);
                mma16816(O[nfd], ph[ks], bvl);
                mma16816(O[nfd], pl[ks], bvh);
            }
        }
        __syncthreads();
    }

    // ---- finalize: O /= l, write bf16 hi/lo in [B,S,E] merged-head layout
    const float i0 = 1.f / lsum0, i1 = 1.f / lsum1;
    const int b = bh >> 4, h = bh & 15;
    uint32_t* Ohi = (uint32_t*)g_Ohi4;
    uint32_t* Olo = (uint32_t*)g_Olo4;
    const long base0 = ((long)(b * SQ + qrow0)) * EMB + h * HD;
    const long base1 = base0 + 8L * EMB;
    #pragma unroll
    for (int nfd = 0; nfd < 8; nfd++) {
        const int col = nfd * 8 + tm4 * 2;
        uint32_t hh, ll;
        split2(O[nfd][0] * i0, O[nfd][1] * i0, hh, ll);
        Ohi[(base0 + col) >> 1] = hh;
        Olo[(base0 + col) >> 1] = ll;
        split2(O[nfd][2] * i1, O[nfd][3] * i1, hh, ll);
        Ohi[(base1 + col) >> 1] = hh;
        Olo[(base1 + col) >> 1] = ll;
    }
}

// ---------------------------------------------------------------------------
extern "C" void kernel_launch(void* const* d_in, const int* in_sizes, int n_in,
                              void* d_out, int out_size)
{
    const float* x      = (const float*)d_in[0];
    const float* W_attn = (const float*)d_in[1];
    const float* b_attn = (const float*)d_in[2];
    const float* W_proj = (const float*)d_in[3];
    const float* b_proj = (const float*)d_in[4];
    float* out = (float*)d_out;

    const int DSM = 2 * STAGEB;          // 147456
    const int ASM_SZ = 256 * AROW;       // 36864
    cudaFuncSetAttribute(k_gemm_qkv,  cudaFuncAttributeMaxDynamicSharedMemorySize, DSM);
    cudaFuncSetAttribute(k_gemm_proj, cudaFuncAttributeMaxDynamicSharedMemorySize, DSM);

    uint4 *xhi, *xlo, *wahi, *walo, *wphi, *wplo;
    cudaGetSymbolAddress((void**)&xhi,  g_Xhi4);
    cudaGetSymbolAddress((void**)&xlo,  g_Xlo4);
    cudaGetSymbolAddress((void**)&wahi, g_WaThi4);
    cudaGetSymbolAddress((void**)&walo, g_WaTlo4);
    cudaGetSymbolAddress((void**)&wphi, g_WpThi4);
    cudaGetSymbolAddress((void**)&wplo, g_WpTlo4);

    k_cvt<<<4096, 256>>>((const float4*)x, (uint2*)xhi, (uint2*)xlo, 4096 * 1024 / 4);
    k_wT<<<dim3(96, 32), dim3(32, 8)>>>(W_attn, 3072, (ushortx*)wahi, (ushortx*)walo);
    k_wT<<<dim3(32, 32), dim3(32, 8)>>>(W_proj, 1024, (ushortx*)wphi, (ushortx*)wplo);
    k_gemm_qkv<<<dim3(24, 32), 256, DSM>>>(b_attn);
    k_attn_mma<<<dim3(8, 64), 256, ASM_SZ>>>();
    k_gemm_proj<<<dim3(8, 32), 256, DSM>>>(b_proj, out);
}